// round 13
// baseline (speedup 1.0000x reference)
#include <cuda_runtime.h>
#include <cstring>

#define GN 512
#define TBR 64          // tile rows
#define TBC 32          // tile cols
#define TD 8            // temporal depth per chunk
#define ROWS_P 82       // padded smem rows (region 80 + ring)
#define COLS_P 56       // float stride: 2-row offset 112 = 16 mod 32 -> conflict-free LDS.128
#define NGRP 12         // 4-column groups per region (48 cols)
#define NT 480          // 12 groups x 40 two-row strips
#define TOTAL_STEPS 199
#define NCHUNK 25       // 24 chunks at 8 + final chunk re-anchored at frame 191
#define N2 (GN * GN)

typedef unsigned long long u64;
typedef ulonglong2 V4;

__device__ unsigned g_flags[8][16];   // [by][bx], cumulative chunks, never reset

__device__ __forceinline__ u64 PKf(float a, float b) {
    float2 t = make_float2(a, b); u64 r; memcpy(&r, &t, 8); return r;
}
__device__ __forceinline__ float2 UPf(u64 v) {
    float2 t; memcpy(&t, &v, 8); return t;
}
__device__ __forceinline__ u64 ADD2(u64 a, u64 b) {
    u64 d; asm("add.rn.f32x2 %0,%1,%2;" : "=l"(d) : "l"(a), "l"(b)); return d;
}
__device__ __forceinline__ u64 MUL2(u64 a, u64 b) {
    u64 d; asm("mul.rn.f32x2 %0,%1,%2;" : "=l"(d) : "l"(a), "l"(b)); return d;
}
__device__ __forceinline__ u64 FMA2(u64 a, u64 b, u64 c) {
    u64 d; asm("fma.rn.f32x2 %0,%1,%2,%3;" : "=l"(d) : "l"(a), "l"(b), "l"(c)); return d;
}
__device__ __forceinline__ unsigned ld_acq(const unsigned* p) {
    unsigned v;
    asm volatile("ld.acquire.gpu.global.u32 %0, [%1];" : "=r"(v) : "l"(p) : "memory");
    return v;
}

// Persistent kernel: 128 CTAs (one per SM, whole grid co-resident -> spinning is
// deadlock-free). Each CTA owns tile (bx,by) for all 25 chunks. Chunk c>0 waits
// until the 3x3 clamped neighborhood has flag >= base+c (they wrote chunk c-1's
// final frame), where base = own flag at kernel entry (monotonic across graph
// replays; every run adds exactly 24, so all tiles are equal at launch start).
// Chunks 0..23 advance frames 0..191; chunk 24 re-anchors at frame 191 (reads
// frame 190, recomputes frame 191 identically) so every chunk is exactly 8 steps
// -> one template instantiation, bounded I-cache. Per-chunk core = proven R12:
// garbage-ringed 80x48 region, fused LDG step 0, f32x2 math on LDS.128 pairs,
// branchless col specials, same-thread row fixups, last step skips STS.
__global__ __launch_bounds__(NT) void adr_persist(
    const float* __restrict__ u0,
    float* __restrict__ frames,
    const float* __restrict__ k1p, const float* __restrict__ k2p,
    const float* __restrict__ a1p, const float* __restrict__ a2p)
{
    __shared__ __align__(16) float buf[2][ROWS_P][COLS_P];

    const float k1 = __ldg(k1p), k2 = __ldg(k2p);
    const float a1 = __ldg(a1p), a2 = __ldg(a2p);
    const float inv_k12 = 1.0f / (k1 + k2);
    const float inv_dx2 = 511.0f * 511.0f;
    const float inv_2dx = 255.5f;
    const float DTC = 1e-7f;

    const int by = blockIdx.y, bx = blockIdx.x;
    const int r0 = by * TBR - TD;
    const int c0 = bx * TBC - TD;
    const int tid = (int)threadIdx.x;
    const int g  = tid % NGRP;
    const int ty = tid / NGRP;
    const int rbase = ty * 2;
    const int gj0 = c0 + 4 * g;
    const int sc  = 4 * g + 4;

    const float kap = (gj0 < 256) ? k1 : k2;
    const float al  = (gj0 < 256) ? a1 : a2;

    const float A1c = DTC * al * inv_dx2;
    const u64 cA1    = PKf(A1c, A1c);
    const u64 c1M4A1 = PKf(1.0f - 4.0f * A1c, 1.0f - 4.0f * A1c);
    const u64 cM1    = PKf(-1.0f, -1.0f);
    const u64 cONE   = PKf(1.0f, 1.0f);
    const u64 cI2    = PKf(inv_2dx, inv_2dx);
    const u64 cMI2   = PKf(-inv_2dx, -inv_2dx);
    const u64 cB1    = PKf(DTC * kap, DTC * kap);

    const bool colC = (g >= 2) && (g <= 9);
    const bool rowC = (ty >= 4) && (ty <= 35);
    const bool storeC = colC && rowC;
    const bool isI  = (gj0 == 252);
    const bool isL  = (gj0 == 0);
    const bool isR  = (gj0 == 508);
    const bool topFix = (by == 0) && (ty == 4);
    const bool botFix = (by == GN / TBR - 1) && (ty == 35);

    auto pointPair = [&](u64 Tm, u64 Tc, u64 Tp, u64 L, u64 R) -> u64 {
        u64 sum  = ADD2(ADD2(Tm, Tp), ADD2(L, R));
        u64 lapc = FMA2(Tc, c1M4A1, MUL2(sum, cA1));
        u64 dxv  = FMA2(Tm, cM1, Tp);
        u64 dyv  = FMA2(L,  cM1, R);
        u64 P    = FMA2(dxv, cMI2, ADD2(Tc, cM1));
        u64 Q    = FMA2(dyv, cI2,  cONE);
        u64 S    = FMA2(MUL2(Tc, Tc), P, MUL2(Tc, Q));
        return FMA2(S, cB1, lapc);
    };

    auto rowcalc = [&](V4 Fm, V4 Fc, V4 Fp, float TlS, float TrS) -> V4 {
        float2 cl = UPf(Fc.x);
        float2 ch = UPf(Fc.y);
        u64 L0 = PKf(TlS, cl.x);
        u64 M  = PKf(cl.y, ch.x);
        u64 R1 = PKf(ch.y, TrS);
        u64 v0 = pointPair(Fm.x, Fc.x, Fp.x, L0, M);
        u64 v1 = pointPair(Fm.y, Fc.y, Fp.y, M, R1);
        float2 vh = UPf(v1);
        float ifv = fmaf(k1, TrS, k2 * ch.x) * inv_k12;  // interface col 255
        vh.y = isI ? ifv : vh.y;
        vh.y = isR ? vh.x : vh.y;                         // col 511 := 510
        v1 = PKf(vh.x, vh.y);
        float2 vl = UPf(v0);
        vl.x = isL ? vl.y : vl.x;                         // col 0 := 1
        v0 = PKf(vl.x, vl.y);
        V4 out; out.x = v0; out.y = v1; return out;
    };

    const bool canVec = (gj0 >= 0) && (gj0 + 3 < GN);
    const int j0 = min(max(gj0 + 0, 0), GN - 1);
    const int j1 = min(max(gj0 + 1, 0), GN - 1);
    const int j2 = min(max(gj0 + 2, 0), GN - 1);
    const int j3 = min(max(gj0 + 3, 0), GN - 1);
    const int jl = min(max(gj0 - 1, 0), GN - 1);
    const int jr = min(max(gj0 + 4, 0), GN - 1);

    // one 8-step chunk: src state -> frames fbase[0..7]
    auto do_chunk = [&](const float* in_state, float* fbase) {
        float* const fr0 = fbase + (ptrdiff_t)(r0 + rbase) * GN + gj0;
        {   // fused global load + step 0
            auto ldrow = [&](int gi) -> V4 {
                int li = min(max(gi, 0), GN - 1);
                if (canVec) return *(const V4*)&in_state[(size_t)li * GN + gj0];
                V4 v;
                v.x = PKf(in_state[(size_t)li * GN + j0], in_state[(size_t)li * GN + j1]);
                v.y = PKf(in_state[(size_t)li * GN + j2], in_state[(size_t)li * GN + j3]);
                return v;
            };
            auto lded = [&](int gi, int jj) -> float {
                int li = min(max(gi, 0), GN - 1);
                return in_state[(size_t)li * GN + jj];
            };
            V4 Fm = ldrow(r0 + rbase - 1);
            V4 F1 = ldrow(r0 + rbase);
            V4 F2 = ldrow(r0 + rbase + 1);
            V4 F3 = ldrow(r0 + rbase + 2);
            float TlA = lded(r0 + rbase,     jl), TrA = lded(r0 + rbase,     jr);
            float TlB = lded(r0 + rbase + 1, jl), TrB = lded(r0 + rbase + 1, jr);

            V4 VA = rowcalc(Fm, F1, F2, TlA, TrA);
            V4 VB = rowcalc(F1, F2, F3, TlB, TrB);

            *(V4*)&buf[0][rbase + 1][sc] = VA;
            *(V4*)&buf[0][rbase + 2][sc] = VB;
            if (storeC) {
                *(V4*)&fr0[0]  = VA;
                *(V4*)&fr0[GN] = VB;
            }
            if (topFix) {
                *(V4*)&buf[0][9][sc] = VB;
                if (colC) *(V4*)&fbase[gj0] = VB;
            }
            if (botFix) {
                *(V4*)&buf[0][72][sc] = VA;
                if (colC) *(V4*)&fbase[(size_t)(GN - 1) * GN + gj0] = VA;
            }
        }
        __syncthreads();

        #pragma unroll
        for (int s = 1; s < TD; ++s) {
            const float (*A)[COLS_P] = buf[(s + 1) & 1];
            float (*B)[COLS_P] = buf[s & 1];
            float* f0 = fr0 + (size_t)s * N2;
            const bool last = (s == TD - 1);

            V4 F0 = *(const V4*)&A[rbase + 0][sc];
            V4 F1 = *(const V4*)&A[rbase + 1][sc];
            V4 F2 = *(const V4*)&A[rbase + 2][sc];
            V4 F3 = *(const V4*)&A[rbase + 3][sc];
            float TlA = A[rbase + 1][sc - 1], TrA = A[rbase + 1][sc + 4];
            float TlB = A[rbase + 2][sc - 1], TrB = A[rbase + 2][sc + 4];

            V4 VA = rowcalc(F0, F1, F2, TlA, TrA);
            V4 VB = rowcalc(F1, F2, F3, TlB, TrB);

            if (!last) {
                *(V4*)&B[rbase + 1][sc] = VA;
                *(V4*)&B[rbase + 2][sc] = VB;
            }
            if (storeC) {
                *(V4*)&f0[0]  = VA;
                *(V4*)&f0[GN] = VB;
            }
            if (topFix) {
                if (!last) *(V4*)&B[9][sc] = VB;
                if (colC) *(V4*)&fbase[(size_t)s * N2 + gj0] = VB;
            }
            if (botFix) {
                if (!last) *(V4*)&B[72][sc] = VA;
                if (colC) *(V4*)&fbase[(size_t)s * N2 + (size_t)(GN - 1) * GN + gj0] = VA;
            }
            if (!last) __syncthreads();
        }
    };

    // epoch base: own flag at entry; all tiles equal at launch start
    const unsigned base = *(volatile unsigned*)&g_flags[by][bx];

    #pragma unroll 1
    for (int c = 0; c < NCHUNK; ++c) {
        if (c > 0) {
            if (tid < 9) {   // wait for 3x3 clamped neighborhood to finish chunk c-1
                int dy = tid / 3 - 1, dx = tid % 3 - 1;
                int nby = min(max(by + dy, 0), 7);
                int nbx = min(max(bx + dx, 0), 15);
                const unsigned thr = base + (unsigned)c;
                while (ld_acq(&g_flags[nby][nbx]) < thr) { }
            }
            __syncthreads();
        }
        const int done = (c < NCHUNK - 1) ? 8 * c : 191;   // chunk 24 re-anchors
        const float* src = (c == 0) ? u0 : frames + (size_t)(done - 1) * N2;
        do_chunk(src, frames + (size_t)done * N2);

        if (c < NCHUNK - 1) {
            __threadfence();      // make this chunk's STGs globally visible
            __syncthreads();      // all threads fenced before the flag bump
            if (tid == 0) atomicAdd(&g_flags[by][bx], 1u);
        }
    }
}

extern "C" void kernel_launch(void* const* d_in, const int* in_sizes, int n_in,
                              void* d_out, int out_size)
{
    (void)in_sizes; (void)n_in; (void)out_size;
    const float* u0 = (const float*)d_in[0];
    const float* k1 = (const float*)d_in[1];
    const float* k2 = (const float*)d_in[2];
    const float* a1 = (const float*)d_in[3];
    const float* a2 = (const float*)d_in[4];
    float* out = (float*)d_out;

    dim3 grid(GN / TBC, GN / TBR);   // 16 x 8 = 128 CTAs, all co-resident
    dim3 block(NT);
    adr_persist<<<grid, block>>>(u0, out, k1, k2, a1, a2);
}